// round 5
// baseline (speedup 1.0000x reference)
#include <cuda_runtime.h>
#include <math.h>

#define PP 2
#define BB 96
#define AA 32
#define NATOM (BB*AA)        // 3072
#define NPOLB 8
#define MD 4
#define MA 4
#define C_LK 0.0897935610625833f
#define JSPLIT 4
#define CHUNK (NATOM/JSPLIT) // 768

struct F3 { float x, y, z; };
__device__ __forceinline__ F3 sub3(F3 a, F3 b){ F3 r; r.x=a.x-b.x; r.y=a.y-b.y; r.z=a.z-b.z; return r; }
__device__ __forceinline__ float dot3(F3 a, F3 b){ return a.x*b.x + a.y*b.y + a.z*b.z; }
__device__ __forceinline__ F3 cross3(F3 a, F3 b){
    F3 r; r.x = a.y*b.z - a.z*b.y; r.y = a.z*b.x - a.x*b.z; r.z = a.x*b.y - a.y*b.x; return r;
}
__device__ __forceinline__ F3 norm3(F3 a){
    float inv = rsqrtf(dot3(a,a) + 1e-12f);
    F3 r; r.x=a.x*inv; r.y=a.y*inv; r.z=a.z*inv; return r;
}

__global__ __launch_bounds__(256, 5)
void lkball_fused_kernel(
    const float* __restrict__ coords,       // (P, N, 3)
    const int*   __restrict__ btype,        // (P, B)
    const int*   __restrict__ msep,         // (P, B, B)
    const int*   __restrict__ bonds,        // (NT, A, 2)
    const int*   __restrict__ ranges,       // (NT, A, 2)
    const int*   __restrict__ n_donH,       // (NT,)
    const int*   __restrict__ n_acc,        // (NT,)
    const int*   __restrict__ donH,         // (NT, MD)
    const int*   __restrict__ donHvy,       // (NT, MD)
    const int*   __restrict__ accI,         // (NT, MA)
    const int*   __restrict__ hyb,          // (NT, MA)
    const int*   __restrict__ isH,          // (NT, A)
    const float* __restrict__ lkp,          // (NT, A, 4)
    const int*   __restrict__ pd,           // (NT, A, A)
    const float* __restrict__ lkg,          // (3,)
    const float* __restrict__ wgp,          // (2,)
    const float* __restrict__ sp2t,         // (2,)
    const float* __restrict__ sp3t,         // (2,)
    const float* __restrict__ ringt,        // (2,)
    float* __restrict__ out)
{
    const int p   = blockIdx.x / BB;
    const int b   = blockIdx.x % BB;
    const int tid = threadIdx.x;

    __shared__ float    sC[AA*3];        // this block's 32 atom coords
    __shared__ int      sBase[AA];       // base_of[a] = bonds1[ranges0[a]]
    __shared__ int      sPol[NPOLB];
    __shared__ unsigned sIm[NPOLB];      // per-site intra sep>=4 mask over aj
    __shared__ unsigned sBp[3];          // 96-bit inter-block sep>=4 mask
    // per-site: [0..2]=xp, [3]=Ki, [4]=inv_lami, [5]=ri, [6..8]=w0, [9..11]=w1
    __shared__ float    sSite[NPOLB][12];
    __shared__ float    sred[2][8];

    const int bt = btype[p*BB + b];
    const float* cb = coords + (p*NATOM + b*AA)*3;

    // ---------- phase 0: parallel staging ----------
    if (tid < 96) {
        sC[tid] = __ldg(cb + tid);
    } else if (tid < 128) {
        int a = tid - 96;
        int rr = __ldg(&ranges[(bt*AA + a)*2]);
        sBase[a] = __ldg(&bonds[(bt*AA + rr)*2 + 1]);
    } else if (tid < 136) {
        int k = tid - 128;
        sPol[k] = (k < MD) ? __ldg(&donHvy[bt*MD + k]) : __ldg(&accI[bt*MA + (k - MD)]);
    } else if (tid >= 160) {             // warps 5-7: inter-block sep ballots
        int lane = tid & 31;
        int w = (tid >> 5) - 5;
        int v = __ldg(&msep[(p*BB + b)*BB + w*32 + lane]);
        unsigned m = __ballot_sync(0xFFFFFFFFu, v >= 4);
        if (lane == 0) sBp[w] = m;
    }
    __syncthreads();

    // ---------- phase 1: pd ballots (all warps) + site geometry (warps 0,1) ----------
    {
        int w = tid >> 5, lane = tid & 31;
        int v = __ldg(&pd[(bt*AA + sPol[w])*AA + lane]);
        unsigned m = __ballot_sync(0xFFFFFFFFu, v >= 4);
        if (lane == 0) sIm[w] = m;
    }

    const bool isDon = (tid < MD);                      // warp 0 lanes 0-3
    const bool isAcc = (tid >= 32 && tid < 32 + MA);    // warp 1 lanes 0-3
    if (isDon | isAcc) {
        const int k = isDon ? tid : (MD + tid - 32);
        const float wdist = wgp[0], wang = wgp[1];
        const int pol = sPol[k];
        F3 w0v, w1v;
        bool valid;

        F3 c; c.x = sC[pol*3]; c.y = sC[pol*3+1]; c.z = sC[pol*3+2];

        if (isDon) {
            int hh = __ldg(&donH[bt*MD + k]);
            valid = (k < __ldg(&n_donH[bt]));
            F3 Hh; Hh.x = sC[hh*3]; Hh.y = sC[hh*3+1]; Hh.z = sC[hh*3+2];
            F3 dv = sub3(Hh, c);
            float s = wdist * rsqrtf(dot3(dv,dv) + 1e-12f);
            w0v.x = c.x + s*dv.x; w0v.y = c.y + s*dv.y; w0v.z = c.z + s*dv.z;
            w1v.x = 1e4f; w1v.y = 1e4f; w1v.z = 1e4f;   // donor water1 invalid sentinel
        } else {
            int m = k - MD;
            valid = (m < __ldg(&n_acc[bt]));
            int base  = sBase[pol];
            int base2 = sBase[base];
            F3 bz; bz.x = sC[base*3];  bz.y = sC[base*3+1];  bz.z = sC[base*3+2];
            F3 az; az.x = sC[base2*3]; az.y = sC[base2*3+1]; az.z = sC[base2*3+2];
            F3 e1 = norm3(sub3(c, bz));
            F3 nv = norm3(cross3(sub3(bz, az), e1));
            F3 e2 = cross3(nv, e1);
            int hy = __ldg(&hyb[bt*MA + m]);
            const float* tors = (hy == 0) ? sp2t : ((hy == 1) ? sp3t : ringt);
            float ct = cosf(wang), st = sinf(wang);
            float c1 = -wdist * ct;
            float t0 = tors[0], t1 = tors[1];
            float c2a = wdist * st * cosf(t0), c3a = wdist * st * sinf(t0);
            float c2b = wdist * st * cosf(t1), c3b = wdist * st * sinf(t1);
            w0v.x = c.x + c1*e1.x + c2a*e2.x + c3a*nv.x;
            w0v.y = c.y + c1*e1.y + c2a*e2.y + c3a*nv.y;
            w0v.z = c.z + c1*e1.z + c2a*e2.z + c3a*nv.z;
            w1v.x = c.x + c1*e1.x + c2b*e2.x + c3b*nv.x;
            w1v.y = c.y + c1*e1.y + c2b*e2.y + c3b*nv.y;
            w1v.z = c.z + c1*e1.z + c2b*e2.z + c3b*nv.z;
        }

        float4 pr = __ldg((const float4*)lkp + bt*AA + pol);  // ri, dgi, lami, vol
        if (valid) {
            sSite[k][0] = c.x; sSite[k][1] = c.y; sSite[k][2] = c.z;
        } else {
            sSite[k][0] = 1e9f; sSite[k][1] = 1e9f; sSite[k][2] = 1e9f;  // never in cutoff
        }
        sSite[k][3] = C_LK * pr.y / pr.z;
        sSite[k][4] = 1.0f / pr.z;
        sSite[k][5] = pr.x;
        sSite[k][6] = w0v.x; sSite[k][7]  = w0v.y; sSite[k][8]  = w0v.z;
        sSite[k][9] = w1v.x; sSite[k][10] = w1v.y; sSite[k][11] = w1v.z;
    }
    __syncthreads();

    // ---------- phase 2: main pairwise loop ----------
    float xpx[NPOLB], xpy[NPOLB], xpz[NPOLB];
    #pragma unroll
    for (int i = 0; i < NPOLB; i++) {
        xpx[i] = sSite[i][0]; xpy[i] = sSite[i][1]; xpz[i] = sSite[i][2];
    }
    const unsigned bp0 = sBp[0], bp1 = sBp[1], bp2 = sBp[2];

    const float cutoff = lkg[0];
    const float cut2   = cutoff * cutoff;
    const float ramp2  = lkg[1];
    const float c0     = lkg[2] + ramp2;   // d2_low + ramp2
    const float invr   = 1.0f / ramp2;

    float s0 = 0.0f, s1 = 0.0f;
    const int j0 = blockIdx.y * CHUNK;
    const int pbase = p * NATOM;

    #pragma unroll
    for (int u = 0; u < CHUNK/256; u++) {
        int j  = j0 + u*256 + tid;
        int bj = j >> 5;                 // warp-uniform (j 32-aligned per warp)
        int aj = j & 31;
        bool same = (bj == b);
        unsigned inter =
            ((bj < 32) ? (bp0 >> bj) : (bj < 64) ? (bp1 >> (bj-32)) : (bp2 >> (bj-64))) & 1u;
        if (!same && !inter) continue;   // warp-uniform skip

        int btj = __ldg(&btype[p*BB + bj]);
        int idx = btj*AA + aj;
        float4 pr = __ldg((const float4*)lkp + idx);       // rj = pr.x, vol = pr.w
        float vj = __ldg(&isH[idx]) ? 0.0f : pr.w;
        const float* cp = coords + (pbase + j)*3;
        float cx = __ldg(cp), cy = __ldg(cp+1), cz = __ldg(cp+2);

        if (vj > 0.0f) {
            #pragma unroll
            for (int i = 0; i < NPOLB; i++) {
                if (same && !((sIm[i] >> aj) & 1u)) continue;   // uniform branch on 'same'
                float dx = xpx[i] - cx;
                float dy = xpy[i] - cy;
                float dz = xpz[i] - cz;
                float d2 = fmaf(dx, dx, fmaf(dy, dy, dz*dz));
                if (d2 < cut2) {
                    d2 = fmaxf(d2, 0.01f);
                    float d  = sqrtf(d2);
                    float Ki = sSite[i][3];
                    float il = sSite[i][4];
                    float ri = sSite[i][5];
                    float x  = (d - ri - pr.x) * il;
                    float lk = __fdividef(Ki * vj * __expf(-x*x), d2);
                    float ax = sSite[i][6] - cx, ay = sSite[i][7]  - cy, az = sSite[i][8]  - cz;
                    float d2a = fmaf(ax, ax, fmaf(ay, ay, az*az));
                    float bx = sSite[i][9] - cx, by = sSite[i][10] - cy, bz = sSite[i][11] - cz;
                    float d2b = fmaf(bx, bx, fmaf(by, by, bz*bz));
                    float dm = fminf(d2a, d2b);
                    float wt = __saturatef((c0 - dm) * invr);
                    float frac = wt * wt * (3.0f - 2.0f*wt);
                    s0 += lk;
                    s1 += lk * frac;
                }
            }
        }
    }

    // ---------- reduction ----------
    #pragma unroll
    for (int off = 16; off > 0; off >>= 1) {
        s0 += __shfl_xor_sync(0xFFFFFFFFu, s0, off);
        s1 += __shfl_xor_sync(0xFFFFFFFFu, s1, off);
    }
    int wid  = tid >> 5;
    int lane = tid & 31;
    if (lane == 0) { sred[0][wid] = s0; sred[1][wid] = s1; }
    __syncthreads();
    if (tid == 0) {
        float t0 = 0.f, t1 = 0.f;
        #pragma unroll
        for (int w = 0; w < 8; w++) { t0 += sred[0][w]; t1 += sred[1][w]; }
        atomicAdd(&out[p],      t0);   // out was zeroed by memsetAsync in the graph
        atomicAdd(&out[PP + p], t1);
    }
}

extern "C" void kernel_launch(void* const* d_in, const int* in_sizes, int n_in,
                              void* d_out, int out_size)
{
    const float* coords = (const float*)d_in[0];
    const int*   btype  = (const int*)  d_in[1];
    const int*   msep   = (const int*)  d_in[2];
    /* d_in[3] = bt_n_atoms (unused, always A) */
    const int*   bonds  = (const int*)  d_in[4];
    const int*   ranges = (const int*)  d_in[5];
    const int*   ndonH  = (const int*)  d_in[6];
    const int*   nacc   = (const int*)  d_in[7];
    const int*   donH   = (const int*)  d_in[8];
    const int*   donHvy = (const int*)  d_in[9];
    const int*   accI   = (const int*)  d_in[10];
    const int*   hyb    = (const int*)  d_in[11];
    const int*   isH    = (const int*)  d_in[12];
    const float* lkp    = (const float*)d_in[13];
    const int*   pd     = (const int*)  d_in[14];
    const float* lkg    = (const float*)d_in[15];
    const float* wgp    = (const float*)d_in[16];
    const float* sp2t   = (const float*)d_in[17];
    const float* sp3t   = (const float*)d_in[18];
    const float* ringt  = (const float*)d_in[19];
    float* out = (float*)d_out;

    cudaMemsetAsync(out, 0, 4 * sizeof(float));

    dim3 grid(PP*BB, JSPLIT);
    lkball_fused_kernel<<<grid, 256>>>(coords, btype, msep, bonds, ranges,
                                       ndonH, nacc, donH, donHvy, accI, hyb, isH,
                                       lkp, pd, lkg, wgp, sp2t, sp3t, ringt, out);
}

// round 8
// speedup vs baseline: 1.3916x; 1.3916x over previous
#include <cuda_runtime.h>
#include <math.h>

#define PP 2
#define BB 96
#define AA 32
#define NATOM (BB*AA)        // 3072
#define NPOLB 8
#define MD 4
#define MA 4
#define C_LK 0.0897935610625833f
#define JSPLIT 4
#define CHUNK (NATOM/JSPLIT) // 768
#define NBLK (PP*BB*JSPLIT)  // 768

// persistent accumulators (zero-init at load; self-resetting every launch)
__device__ float    g_acc[4];
__device__ unsigned g_cnt;

struct F3 { float x, y, z; };
__device__ __forceinline__ F3 sub3(F3 a, F3 b){ F3 r; r.x=a.x-b.x; r.y=a.y-b.y; r.z=a.z-b.z; return r; }
__device__ __forceinline__ float dot3(F3 a, F3 b){ return a.x*b.x + a.y*b.y + a.z*b.z; }
__device__ __forceinline__ F3 cross3(F3 a, F3 b){
    F3 r; r.x = a.y*b.z - a.z*b.y; r.y = a.z*b.x - a.x*b.z; r.z = a.x*b.y - a.y*b.x; return r;
}
__device__ __forceinline__ F3 norm3(F3 a){
    float inv = rsqrtf(dot3(a,a) + 1e-12f);
    F3 r; r.x=a.x*inv; r.y=a.y*inv; r.z=a.z*inv; return r;
}

__global__ __launch_bounds__(256, 5)
void lkball_fused_kernel(
    const float* __restrict__ coords,       // (P, N, 3)
    const int*   __restrict__ btype,        // (P, B)
    const int*   __restrict__ msep,         // (P, B, B)
    const int*   __restrict__ bonds,        // (NT, A, 2)
    const int*   __restrict__ ranges,       // (NT, A, 2)
    const int*   __restrict__ n_donH,       // (NT,)
    const int*   __restrict__ n_acc,        // (NT,)
    const int*   __restrict__ donH,         // (NT, MD)
    const int*   __restrict__ donHvy,       // (NT, MD)
    const int*   __restrict__ accI,         // (NT, MA)
    const int*   __restrict__ hyb,          // (NT, MA)
    const int*   __restrict__ isH,          // (NT, A)
    const float* __restrict__ lkp,          // (NT, A, 4)
    const int*   __restrict__ pd,           // (NT, A, A)
    const float* __restrict__ lkg,          // (3,)
    const float* __restrict__ wgp,          // (2,)
    const float* __restrict__ sp2t,         // (2,)
    const float* __restrict__ sp3t,         // (2,)
    const float* __restrict__ ringt,        // (2,)
    float* __restrict__ out)
{
    const int p   = blockIdx.x / BB;
    const int b   = blockIdx.x % BB;
    const int tid = threadIdx.x;

    __shared__ float    sC[AA*3];        // this block's 32 atom coords
    __shared__ int      sBase[AA];       // base_of[a] = bonds1[ranges0[a]]
    __shared__ int      sPol[NPOLB];
    __shared__ unsigned sIm[NPOLB];      // per-site intra sep>=4 mask over aj
    __shared__ unsigned sBp[3];          // 96-bit inter-block sep>=4 mask
    // per-site: [0..2]=xp, [3]=Ki, [4]=inv_lami, [5]=ri, [6..8]=w0, [9..11]=w1
    __shared__ float    sSite[NPOLB][12];
    __shared__ float    sred[2][8];

    const int bt = btype[p*BB + b];
    const float* cb = coords + (p*NATOM + b*AA)*3;

    // ---------- phase 0: parallel staging ----------
    if (tid < 96) {
        sC[tid] = __ldg(cb + tid);
    } else if (tid < 128) {
        int a = tid - 96;
        int rr = __ldg(&ranges[(bt*AA + a)*2]);
        sBase[a] = __ldg(&bonds[(bt*AA + rr)*2 + 1]);
    } else if (tid < 136) {
        int k = tid - 128;
        sPol[k] = (k < MD) ? __ldg(&donHvy[bt*MD + k]) : __ldg(&accI[bt*MA + (k - MD)]);
    } else if (tid >= 160) {             // warps 5-7: inter-block sep ballots
        int lane = tid & 31;
        int w = (tid >> 5) - 5;
        int v = __ldg(&msep[(p*BB + b)*BB + w*32 + lane]);
        unsigned m = __ballot_sync(0xFFFFFFFFu, v >= 4);
        if (lane == 0) sBp[w] = m;
    }
    __syncthreads();

    // ---------- phase 1: pd ballots (all warps) + site geometry (warps 0,1) ----------
    {
        int w = tid >> 5, lane = tid & 31;
        int v = __ldg(&pd[(bt*AA + sPol[w])*AA + lane]);
        unsigned m = __ballot_sync(0xFFFFFFFFu, v >= 4);
        if (lane == 0) sIm[w] = m;
    }

    const bool isDon = (tid < MD);                      // warp 0 lanes 0-3
    const bool isAcc = (tid >= 32 && tid < 32 + MA);    // warp 1 lanes 0-3
    if (isDon | isAcc) {
        const int k = isDon ? tid : (MD + tid - 32);
        const float wdist = wgp[0], wang = wgp[1];
        const int pol = sPol[k];
        F3 w0v, w1v;
        bool valid;

        F3 c; c.x = sC[pol*3]; c.y = sC[pol*3+1]; c.z = sC[pol*3+2];

        if (isDon) {
            int hh = __ldg(&donH[bt*MD + k]);
            valid = (k < __ldg(&n_donH[bt]));
            F3 Hh; Hh.x = sC[hh*3]; Hh.y = sC[hh*3+1]; Hh.z = sC[hh*3+2];
            F3 dv = sub3(Hh, c);
            float s = wdist * rsqrtf(dot3(dv,dv) + 1e-12f);
            w0v.x = c.x + s*dv.x; w0v.y = c.y + s*dv.y; w0v.z = c.z + s*dv.z;
            w1v.x = 1e4f; w1v.y = 1e4f; w1v.z = 1e4f;   // donor water1 invalid sentinel
        } else {
            int m = k - MD;
            valid = (m < __ldg(&n_acc[bt]));
            int base  = sBase[pol];
            int base2 = sBase[base];
            F3 bz; bz.x = sC[base*3];  bz.y = sC[base*3+1];  bz.z = sC[base*3+2];
            F3 az; az.x = sC[base2*3]; az.y = sC[base2*3+1]; az.z = sC[base2*3+2];
            F3 e1 = norm3(sub3(c, bz));
            F3 nv = norm3(cross3(sub3(bz, az), e1));
            F3 e2 = cross3(nv, e1);
            int hy = __ldg(&hyb[bt*MA + m]);
            const float* tors = (hy == 0) ? sp2t : ((hy == 1) ? sp3t : ringt);
            float ct = cosf(wang), st = sinf(wang);
            float c1 = -wdist * ct;
            float t0 = tors[0], t1 = tors[1];
            float c2a = wdist * st * cosf(t0), c3a = wdist * st * sinf(t0);
            float c2b = wdist * st * cosf(t1), c3b = wdist * st * sinf(t1);
            w0v.x = c.x + c1*e1.x + c2a*e2.x + c3a*nv.x;
            w0v.y = c.y + c1*e1.y + c2a*e2.y + c3a*nv.y;
            w0v.z = c.z + c1*e1.z + c2a*e2.z + c3a*nv.z;
            w1v.x = c.x + c1*e1.x + c2b*e2.x + c3b*nv.x;
            w1v.y = c.y + c1*e1.y + c2b*e2.y + c3b*nv.y;
            w1v.z = c.z + c1*e1.z + c2b*e2.z + c3b*nv.z;
        }

        float4 pr = __ldg((const float4*)lkp + bt*AA + pol);  // ri, dgi, lami, vol
        if (valid) {
            sSite[k][0] = c.x; sSite[k][1] = c.y; sSite[k][2] = c.z;
        } else {
            sSite[k][0] = 1e9f; sSite[k][1] = 1e9f; sSite[k][2] = 1e9f;  // never in cutoff
        }
        sSite[k][3] = C_LK * pr.y / pr.z;
        sSite[k][4] = 1.0f / pr.z;
        sSite[k][5] = pr.x;
        sSite[k][6] = w0v.x; sSite[k][7]  = w0v.y; sSite[k][8]  = w0v.z;
        sSite[k][9] = w1v.x; sSite[k][10] = w1v.y; sSite[k][11] = w1v.z;
    }
    __syncthreads();

    // ---------- phase 2: main pairwise loop ----------
    float xpx[NPOLB], xpy[NPOLB], xpz[NPOLB];
    #pragma unroll
    for (int i = 0; i < NPOLB; i++) {
        xpx[i] = sSite[i][0]; xpy[i] = sSite[i][1]; xpz[i] = sSite[i][2];
    }
    const unsigned bp0 = sBp[0], bp1 = sBp[1], bp2 = sBp[2];

    const float cutoff = lkg[0];
    const float cut2   = cutoff * cutoff;
    const float ramp2  = lkg[1];
    const float c0     = lkg[2] + ramp2;   // d2_low + ramp2
    const float invr   = 1.0f / ramp2;

    float s0 = 0.0f, s1 = 0.0f;
    const int j0 = blockIdx.y * CHUNK;
    const int pbase = p * NATOM;

    #pragma unroll
    for (int u = 0; u < CHUNK/256; u++) {
        int j  = j0 + u*256 + tid;
        int bj = j >> 5;                 // warp-uniform (j 32-aligned per warp)
        int aj = j & 31;
        bool same = (bj == b);
        unsigned inter =
            ((bj < 32) ? (bp0 >> bj) : (bj < 64) ? (bp1 >> (bj-32)) : (bp2 >> (bj-64))) & 1u;
        if (!same && !inter) continue;   // warp-uniform skip

        int btj = __ldg(&btype[p*BB + bj]);
        int idx = btj*AA + aj;
        float4 pr = __ldg((const float4*)lkp + idx);       // rj = pr.x, vol = pr.w
        float vj = __ldg(&isH[idx]) ? 0.0f : pr.w;
        const float* cp = coords + (pbase + j)*3;
        float cx = __ldg(cp), cy = __ldg(cp+1), cz = __ldg(cp+2);

        if (vj > 0.0f) {
            #pragma unroll
            for (int i = 0; i < NPOLB; i++) {
                if (same && !((sIm[i] >> aj) & 1u)) continue;   // uniform branch on 'same'
                float dx = xpx[i] - cx;
                float dy = xpy[i] - cy;
                float dz = xpz[i] - cz;
                float d2 = fmaf(dx, dx, fmaf(dy, dy, dz*dz));
                if (d2 < cut2) {
                    d2 = fmaxf(d2, 0.01f);
                    float d  = sqrtf(d2);
                    float Ki = sSite[i][3];
                    float il = sSite[i][4];
                    float ri = sSite[i][5];
                    float x  = (d - ri - pr.x) * il;
                    float lk = __fdividef(Ki * vj * __expf(-x*x), d2);
                    float ax = sSite[i][6] - cx, ay = sSite[i][7]  - cy, az = sSite[i][8]  - cz;
                    float d2a = fmaf(ax, ax, fmaf(ay, ay, az*az));
                    float bx = sSite[i][9] - cx, by = sSite[i][10] - cy, bz = sSite[i][11] - cz;
                    float d2b = fmaf(bx, bx, fmaf(by, by, bz*bz));
                    float dm = fminf(d2a, d2b);
                    float wt = __saturatef((c0 - dm) * invr);
                    float frac = wt * wt * (3.0f - 2.0f*wt);
                    s0 += lk;
                    s1 += lk * frac;
                }
            }
        }
    }

    // ---------- reduction + self-resetting global accumulation (single node!) ----------
    #pragma unroll
    for (int off = 16; off > 0; off >>= 1) {
        s0 += __shfl_xor_sync(0xFFFFFFFFu, s0, off);
        s1 += __shfl_xor_sync(0xFFFFFFFFu, s1, off);
    }
    int wid  = tid >> 5;
    int lane = tid & 31;
    if (lane == 0) { sred[0][wid] = s0; sred[1][wid] = s1; }
    __syncthreads();
    if (tid == 0) {
        float t0 = 0.f, t1 = 0.f;
        #pragma unroll
        for (int w = 0; w < 8; w++) { t0 += sred[0][w]; t1 += sred[1][w]; }
        atomicAdd(&g_acc[p],     t0);
        atomicAdd(&g_acc[2 + p], t1);
        __threadfence();
        unsigned done = atomicAdd(&g_cnt, 1u);
        if (done == NBLK - 1) {
            // last CTA: drain + reset accumulators, write output (2, P) row-major
            out[0] = atomicExch(&g_acc[0], 0.0f);
            out[1] = atomicExch(&g_acc[1], 0.0f);
            out[2] = atomicExch(&g_acc[2], 0.0f);
            out[3] = atomicExch(&g_acc[3], 0.0f);
            atomicExch(&g_cnt, 0u);
        }
    }
}

extern "C" void kernel_launch(void* const* d_in, const int* in_sizes, int n_in,
                              void* d_out, int out_size)
{
    const float* coords = (const float*)d_in[0];
    const int*   btype  = (const int*)  d_in[1];
    const int*   msep   = (const int*)  d_in[2];
    /* d_in[3] = bt_n_atoms (unused, always A) */
    const int*   bonds  = (const int*)  d_in[4];
    const int*   ranges = (const int*)  d_in[5];
    const int*   ndonH  = (const int*)  d_in[6];
    const int*   nacc   = (const int*)  d_in[7];
    const int*   donH   = (const int*)  d_in[8];
    const int*   donHvy = (const int*)  d_in[9];
    const int*   accI   = (const int*)  d_in[10];
    const int*   hyb    = (const int*)  d_in[11];
    const int*   isH    = (const int*)  d_in[12];
    const float* lkp    = (const float*)d_in[13];
    const int*   pd     = (const int*)  d_in[14];
    const float* lkg    = (const float*)d_in[15];
    const float* wgp    = (const float*)d_in[16];
    const float* sp2t   = (const float*)d_in[17];
    const float* sp3t   = (const float*)d_in[18];
    const float* ringt  = (const float*)d_in[19];
    float* out = (float*)d_out;

    dim3 grid(PP*BB, JSPLIT);
    lkball_fused_kernel<<<grid, 256>>>(coords, btype, msep, bonds, ranges,
                                       ndonH, nacc, donH, donHvy, accI, hyb, isH,
                                       lkp, pd, lkg, wgp, sp2t, sp3t, ringt, out);
}

// round 11
// speedup vs baseline: 1.4438x; 1.0375x over previous
#include <cuda_runtime.h>
#include <math.h>

#define PP 2
#define BB 96
#define AA 32
#define NATOM (BB*AA)        // 3072
#define NPOLB 8
#define MD 4
#define MA 4
#define C_LK 0.0897935610625833f
#define JSPLIT 4
#define CHUNK (NATOM/JSPLIT) // 768
#define NBLK (PP*BB*JSPLIT)  // 768

// persistent accumulators (zero-init at load; self-resetting every launch)
__device__ float    g_acc[4];
__device__ unsigned g_cnt;

struct F3 { float x, y, z; };
__device__ __forceinline__ F3 sub3(F3 a, F3 b){ F3 r; r.x=a.x-b.x; r.y=a.y-b.y; r.z=a.z-b.z; return r; }
__device__ __forceinline__ float dot3(F3 a, F3 b){ return a.x*b.x + a.y*b.y + a.z*b.z; }
__device__ __forceinline__ F3 cross3(F3 a, F3 b){
    F3 r; r.x = a.y*b.z - a.z*b.y; r.y = a.z*b.x - a.x*b.z; r.z = a.x*b.y - a.y*b.x; return r;
}
__device__ __forceinline__ F3 norm3(F3 a){
    float inv = rsqrtf(dot3(a,a) + 1e-12f);
    F3 r; r.x=a.x*inv; r.y=a.y*inv; r.z=a.z*inv; return r;
}

__global__ __launch_bounds__(256, 5)
void lkball_fused_kernel(
    const float* __restrict__ coords,       // (P, N, 3)
    const int*   __restrict__ btype,        // (P, B)
    const int*   __restrict__ msep,         // (P, B, B)
    const int*   __restrict__ bonds,        // (NT, A, 2)
    const int*   __restrict__ ranges,       // (NT, A, 2)
    const int*   __restrict__ n_donH,       // (NT,)
    const int*   __restrict__ n_acc,        // (NT,)
    const int*   __restrict__ donH,         // (NT, MD)
    const int*   __restrict__ donHvy,       // (NT, MD)
    const int*   __restrict__ accI,         // (NT, MA)
    const int*   __restrict__ hyb,          // (NT, MA)
    const int*   __restrict__ isH,          // (NT, A)
    const float* __restrict__ lkp,          // (NT, A, 4)
    const int*   __restrict__ pd,           // (NT, A, A)
    const float* __restrict__ lkg,          // (3,)
    const float* __restrict__ wgp,          // (2,)
    const float* __restrict__ sp2t,         // (2,)
    const float* __restrict__ sp3t,         // (2,)
    const float* __restrict__ ringt,        // (2,)
    float* __restrict__ out)
{
    const int p    = blockIdx.x / BB;
    const int b    = blockIdx.x % BB;
    const int tid  = threadIdx.x;
    const int wid  = tid >> 5;
    const int lane = tid & 31;

    __shared__ float4        sJ[CHUNK];      // x,y,z,rj for this CTA's j-chunk (12KB)
    __shared__ float         sVol[CHUNK];    // volj (0 for hydrogens)          (3KB)
    __shared__ int           sQ[8][64];      // per-warp compaction queues      (2KB)
    __shared__ float4        sP [NPOLB];     // xp.xyz, Ki
    __shared__ float4        sW0[NPOLB];     // w0.xyz, inv_lami
    __shared__ float4        sW1[NPOLB];     // w1.xyz, ri
    __shared__ float         sC[AA*3];       // this block's 32 atom coords
    __shared__ int           sBase[AA];      // base_of[a] = bonds1[ranges0[a]]
    __shared__ int           sPol[NPOLB];
    __shared__ unsigned      sIm[NPOLB];     // per-site intra sep>=4 mask over aj
    __shared__ unsigned char sSame[AA];      // per-aj 8-bit site mask (intra)
    __shared__ unsigned      sBp[3];         // 96-bit inter-block sep>=4 mask
    __shared__ float         sred[2][8];

    const int bt = btype[p*BB + b];
    const float* cb = coords + (p*NATOM + b*AA)*3;
    const int j0 = blockIdx.y * CHUNK;
    const int pbase = p * NATOM;

    // ---------- phase 0: role-split staging of per-block data ----------
    if (tid < 96) {
        sC[tid] = __ldg(cb + tid);
    } else if (tid < 128) {
        int a = tid - 96;
        int rr = __ldg(&ranges[(bt*AA + a)*2]);
        sBase[a] = __ldg(&bonds[(bt*AA + rr)*2 + 1]);
    } else if (tid < 136) {
        int k = tid - 128;
        sPol[k] = (k < MD) ? __ldg(&donHvy[bt*MD + k]) : __ldg(&accI[bt*MA + (k - MD)]);
    } else if (tid >= 160) {             // warps 5-7: inter-block sep ballots
        int l = tid & 31;
        int w = (tid >> 5) - 5;
        int v = __ldg(&msep[(p*BB + b)*BB + w*32 + l]);
        unsigned m = __ballot_sync(0xFFFFFFFFu, v >= 4);
        if (l == 0) sBp[w] = m;
    }

    // ---------- stage j-chunk into shared (all threads, independent) ----------
    #pragma unroll
    for (int u = 0; u < CHUNK/256; u++) {
        int k = u*256 + tid;
        int j = j0 + k;
        int bj = j >> 5, aj = j & 31;
        int btj = __ldg(&btype[p*BB + bj]);
        int idx = btj*AA + aj;
        float4 pr = __ldg((const float4*)lkp + idx);   // ri, dgi, lami, vol
        const float* cp = coords + (pbase + j)*3;
        float4 q;
        q.x = __ldg(cp); q.y = __ldg(cp+1); q.z = __ldg(cp+2); q.w = pr.x;
        sJ[k] = q;
        sVol[k] = __ldg(&isH[idx]) ? 0.0f : pr.w;
    }
    __syncthreads();

    // ---------- phase 1: pd ballots (all warps) + site geometry (warps 0,1) ----------
    {
        int v = __ldg(&pd[(bt*AA + sPol[wid])*AA + lane]);
        unsigned m = __ballot_sync(0xFFFFFFFFu, v >= 4);
        if (lane == 0) sIm[wid] = m;
    }

    const bool isDon = (tid < MD);                      // warp 0 lanes 0-3
    const bool isAcc = (tid >= 32 && tid < 32 + MA);    // warp 1 lanes 0-3
    if (isDon | isAcc) {
        const int k = isDon ? tid : (MD + tid - 32);
        const float wdist = wgp[0], wang = wgp[1];
        const int pol = sPol[k];
        F3 w0v, w1v;
        bool valid;

        F3 c; c.x = sC[pol*3]; c.y = sC[pol*3+1]; c.z = sC[pol*3+2];

        if (isDon) {
            int hh = __ldg(&donH[bt*MD + k]);
            valid = (k < __ldg(&n_donH[bt]));
            F3 Hh; Hh.x = sC[hh*3]; Hh.y = sC[hh*3+1]; Hh.z = sC[hh*3+2];
            F3 dv = sub3(Hh, c);
            float s = wdist * rsqrtf(dot3(dv,dv) + 1e-12f);
            w0v.x = c.x + s*dv.x; w0v.y = c.y + s*dv.y; w0v.z = c.z + s*dv.z;
            w1v.x = 1e4f; w1v.y = 1e4f; w1v.z = 1e4f;   // donor water1 invalid sentinel
        } else {
            int m = k - MD;
            valid = (m < __ldg(&n_acc[bt]));
            int base  = sBase[pol];
            int base2 = sBase[base];
            F3 bz; bz.x = sC[base*3];  bz.y = sC[base*3+1];  bz.z = sC[base*3+2];
            F3 az; az.x = sC[base2*3]; az.y = sC[base2*3+1]; az.z = sC[base2*3+2];
            F3 e1 = norm3(sub3(c, bz));
            F3 nv = norm3(cross3(sub3(bz, az), e1));
            F3 e2 = cross3(nv, e1);
            int hy = __ldg(&hyb[bt*MA + m]);
            const float* tors = (hy == 0) ? sp2t : ((hy == 1) ? sp3t : ringt);
            float ct = cosf(wang), st = sinf(wang);
            float c1 = -wdist * ct;
            float t0 = tors[0], t1 = tors[1];
            float c2a = wdist * st * cosf(t0), c3a = wdist * st * sinf(t0);
            float c2b = wdist * st * cosf(t1), c3b = wdist * st * sinf(t1);
            w0v.x = c.x + c1*e1.x + c2a*e2.x + c3a*nv.x;
            w0v.y = c.y + c1*e1.y + c2a*e2.y + c3a*nv.y;
            w0v.z = c.z + c1*e1.z + c2a*e2.z + c3a*nv.z;
            w1v.x = c.x + c1*e1.x + c2b*e2.x + c3b*nv.x;
            w1v.y = c.y + c1*e1.y + c2b*e2.y + c3b*nv.y;
            w1v.z = c.z + c1*e1.z + c2b*e2.z + c3b*nv.z;
        }

        float4 pr = __ldg((const float4*)lkp + bt*AA + pol);  // ri, dgi, lami, vol
        float4 P4, W04, W14;
        if (valid) { P4.x = c.x; P4.y = c.y; P4.z = c.z; }
        else       { P4.x = 1e9f; P4.y = 1e9f; P4.z = 1e9f; }   // never within cutoff
        P4.w  = C_LK * pr.y / pr.z;       // Ki
        W04.x = w0v.x; W04.y = w0v.y; W04.z = w0v.z; W04.w = 1.0f / pr.z;  // inv_lami
        W14.x = w1v.x; W14.y = w1v.y; W14.z = w1v.z; W14.w = pr.x;         // ri
        sP [k] = P4;
        sW0[k] = W04;
        sW1[k] = W14;
    }
    __syncthreads();

    // ---------- transpose intra masks to per-aj site bytes ----------
    if (tid < AA) {
        unsigned byte = 0;
        #pragma unroll
        for (int i = 0; i < NPOLB; i++) byte |= ((sIm[i] >> tid) & 1u) << i;
        sSame[tid] = (unsigned char)byte;
    }
    __syncthreads();

    // ---------- phase 2: light loop + compaction queue ----------
    float xpx[NPOLB], xpy[NPOLB], xpz[NPOLB];
    #pragma unroll
    for (int i = 0; i < NPOLB; i++) {
        float4 P4 = sP[i];
        xpx[i] = P4.x; xpy[i] = P4.y; xpz[i] = P4.z;
    }
    const unsigned bp0 = sBp[0], bp1 = sBp[1], bp2 = sBp[2];

    const float cutoff = lkg[0];
    const float cut2   = cutoff * cutoff;
    const float ramp2  = lkg[1];
    const float c0     = lkg[2] + ramp2;   // d2_low + ramp2
    const float invr   = 1.0f / ramp2;

    float s0 = 0.0f, s1 = 0.0f;

    // heavy-path worker: full warp (flush) or partial (drain)
    auto processE = [&](int e) {
        int i  = e >> 10;
        int jj = e & 1023;
        float4 J  = sJ[jj];
        float  vj = sVol[jj];
        float4 Pq = sP[i];
        float4 W0 = sW0[i];
        float4 W1 = sW1[i];
        float dx = Pq.x - J.x, dy = Pq.y - J.y, dz = Pq.z - J.z;
        float d2 = fmaf(dx, dx, fmaf(dy, dy, dz*dz));
        d2 = fmaxf(d2, 0.01f);
        float d  = sqrtf(d2);
        float x  = (d - W1.w - J.w) * W0.w;
        float lk = __fdividef(Pq.w * vj * __expf(-x*x), d2);
        float ax = W0.x - J.x, ay = W0.y - J.y, az = W0.z - J.z;
        float d2a = fmaf(ax, ax, fmaf(ay, ay, az*az));
        float bx = W1.x - J.x, by = W1.y - J.y, bz = W1.z - J.z;
        float d2b = fmaf(bx, bx, fmaf(by, by, bz*bz));
        float dm = fminf(d2a, d2b);
        float wt = __saturatef((c0 - dm) * invr);
        float fr = wt * wt * (3.0f - 2.0f*wt);
        s0 += lk;
        s1 += lk * fr;
    };

    int qc = 0;                              // warp-uniform queue count
    const unsigned ltm = (1u << lane) - 1u;

    #pragma unroll
    for (int u = 0; u < CHUNK/256; u++) {
        int jj = u*256 + tid;
        int j  = j0 + jj;
        int bj = j >> 5;                     // warp-uniform
        int aj = jj & 31;
        bool same = (bj == b);
        unsigned inter =
            ((bj < 32) ? (bp0 >> bj) : (bj < 64) ? (bp1 >> (bj-32)) : (bp2 >> (bj-64))) & 1u;
        if (!same && !inter) continue;       // warp-uniform skip

        float4 J = sJ[jj];
        float vj = sVol[jj];
        unsigned mask = (vj > 0.0f) ? (same ? (unsigned)sSame[aj] : 0xFFu) : 0u;

        #pragma unroll
        for (int i = 0; i < NPOLB; i++) {
            float dx = xpx[i] - J.x;
            float dy = xpy[i] - J.y;
            float dz = xpz[i] - J.z;
            float d2 = fmaf(dx, dx, fmaf(dy, dy, dz*dz));
            bool ok = ((mask >> i) & 1u) && (d2 < cut2);
            unsigned mv = __ballot_sync(0xFFFFFFFFu, ok);
            if (mv) {
                if (ok) sQ[wid][qc + __popc(mv & ltm)] = (i << 10) | jj;
                qc += __popc(mv);
                if (qc >= 32) {              // warp-uniform flush, full efficiency
                    qc -= 32;
                    processE(sQ[wid][qc + lane]);
                }
            }
        }
    }
    if (lane < qc) processE(sQ[wid][lane]);  // drain leftovers (<32)

    // ---------- reduction + self-resetting global accumulation (single node) ----------
    #pragma unroll
    for (int off = 16; off > 0; off >>= 1) {
        s0 += __shfl_xor_sync(0xFFFFFFFFu, s0, off);
        s1 += __shfl_xor_sync(0xFFFFFFFFu, s1, off);
    }
    if (lane == 0) { sred[0][wid] = s0; sred[1][wid] = s1; }
    __syncthreads();
    if (tid == 0) {
        float t0 = 0.f, t1 = 0.f;
        #pragma unroll
        for (int w = 0; w < 8; w++) { t0 += sred[0][w]; t1 += sred[1][w]; }
        atomicAdd(&g_acc[p],     t0);
        atomicAdd(&g_acc[2 + p], t1);
        __threadfence();
        unsigned done = atomicAdd(&g_cnt, 1u);
        if (done == NBLK - 1) {
            out[0] = atomicExch(&g_acc[0], 0.0f);
            out[1] = atomicExch(&g_acc[1], 0.0f);
            out[2] = atomicExch(&g_acc[2], 0.0f);
            out[3] = atomicExch(&g_acc[3], 0.0f);
            atomicExch(&g_cnt, 0u);
        }
    }
}

extern "C" void kernel_launch(void* const* d_in, const int* in_sizes, int n_in,
                              void* d_out, int out_size)
{
    const float* coords = (const float*)d_in[0];
    const int*   btype  = (const int*)  d_in[1];
    const int*   msep   = (const int*)  d_in[2];
    /* d_in[3] = bt_n_atoms (unused, always A) */
    const int*   bonds  = (const int*)  d_in[4];
    const int*   ranges = (const int*)  d_in[5];
    const int*   ndonH  = (const int*)  d_in[6];
    const int*   nacc   = (const int*)  d_in[7];
    const int*   donH   = (const int*)  d_in[8];
    const int*   donHvy = (const int*)  d_in[9];
    const int*   accI   = (const int*)  d_in[10];
    const int*   hyb    = (const int*)  d_in[11];
    const int*   isH    = (const int*)  d_in[12];
    const float* lkp    = (const float*)d_in[13];
    const int*   pd     = (const int*)  d_in[14];
    const float* lkg    = (const float*)d_in[15];
    const float* wgp    = (const float*)d_in[16];
    const float* sp2t   = (const float*)d_in[17];
    const float* sp3t   = (const float*)d_in[18];
    const float* ringt  = (const float*)d_in[19];
    float* out = (float*)d_out;

    dim3 grid(PP*BB, JSPLIT);
    lkball_fused_kernel<<<grid, 256>>>(coords, btype, msep, bonds, ranges,
                                       ndonH, nacc, donH, donHvy, accI, hyb, isH,
                                       lkp, pd, lkg, wgp, sp2t, sp3t, ringt, out);
}

// round 13
// speedup vs baseline: 1.5635x; 1.0829x over previous
#include <cuda_runtime.h>
#include <math.h>

#define PP 2
#define BB 96
#define AA 32
#define NATOM (BB*AA)        // 3072
#define NPOLB 8
#define MD 4
#define MA 4
#define C_LK 0.0897935610625833f
#define JSPLIT 4
#define CHUNK (NATOM/JSPLIT) // 768
#define NBLK (PP*BB*JSPLIT)  // 768
#define QCAP 288             // 31 carry + 256 worst-case appends

// persistent accumulators (zero-init at load; self-resetting every launch)
__device__ float    g_acc[4];
__device__ unsigned g_cnt;

struct F3 { float x, y, z; };
__device__ __forceinline__ F3 sub3(F3 a, F3 b){ F3 r; r.x=a.x-b.x; r.y=a.y-b.y; r.z=a.z-b.z; return r; }
__device__ __forceinline__ float dot3(F3 a, F3 b){ return a.x*b.x + a.y*b.y + a.z*b.z; }
__device__ __forceinline__ F3 cross3(F3 a, F3 b){
    F3 r; r.x = a.y*b.z - a.z*b.y; r.y = a.z*b.x - a.x*b.z; r.z = a.x*b.y - a.y*b.x; return r;
}
__device__ __forceinline__ F3 norm3(F3 a){
    float inv = rsqrtf(dot3(a,a) + 1e-12f);
    F3 r; r.x=a.x*inv; r.y=a.y*inv; r.z=a.z*inv; return r;
}

__global__ __launch_bounds__(256, 5)
void lkball_fused_kernel(
    const float* __restrict__ coords,       // (P, N, 3)
    const int*   __restrict__ btype,        // (P, B)
    const int*   __restrict__ msep,         // (P, B, B)
    const int*   __restrict__ bonds,        // (NT, A, 2)
    const int*   __restrict__ ranges,       // (NT, A, 2)
    const int*   __restrict__ n_donH,       // (NT,)
    const int*   __restrict__ n_acc,        // (NT,)
    const int*   __restrict__ donH,         // (NT, MD)
    const int*   __restrict__ donHvy,       // (NT, MD)
    const int*   __restrict__ accI,         // (NT, MA)
    const int*   __restrict__ hyb,          // (NT, MA)
    const int*   __restrict__ isH,          // (NT, A)
    const float* __restrict__ lkp,          // (NT, A, 4)
    const int*   __restrict__ pd,           // (NT, A, A)
    const float* __restrict__ lkg,          // (3,)
    const float* __restrict__ wgp,          // (2,)
    const float* __restrict__ sp2t,         // (2,)
    const float* __restrict__ sp3t,         // (2,)
    const float* __restrict__ ringt,        // (2,)
    float* __restrict__ out)
{
    const int p    = blockIdx.x / BB;
    const int b    = blockIdx.x % BB;
    const int tid  = threadIdx.x;
    const int wid  = tid >> 5;
    const int lane = tid & 31;

    __shared__ float4        sJ[CHUNK];      // x,y,z,rj for this CTA's j-chunk (12KB)
    __shared__ float         sVol[CHUNK];    // volj (0 for hydrogens)          (3KB)
    __shared__ int           sQ[8][QCAP];    // per-warp compaction queues      (9KB)
    __shared__ float4        sP [NPOLB];     // xp.xyz, Ki
    __shared__ float4        sW0[NPOLB];     // w0.xyz, inv_lami
    __shared__ float4        sW1[NPOLB];     // w1.xyz, ri
    __shared__ float         sC[AA*3];       // this block's 32 atom coords
    __shared__ int           sBase[AA];      // base_of[a] = bonds1[ranges0[a]]
    __shared__ int           sPol[NPOLB];
    __shared__ unsigned      sIm[NPOLB];     // per-site intra sep>=4 mask over aj
    __shared__ unsigned char sSame[AA];      // per-aj 8-bit site mask (intra)
    __shared__ unsigned      sBp[3];         // 96-bit inter-block sep>=4 mask
    __shared__ float         sred[2][8];

    const int bt = btype[p*BB + b];
    const float* cb = coords + (p*NATOM + b*AA)*3;
    const int j0 = blockIdx.y * CHUNK;
    const int pbase = p * NATOM;

    // ---------- phase 0: role-split staging of per-block data ----------
    if (tid < 96) {
        sC[tid] = __ldg(cb + tid);
    } else if (tid < 128) {
        int a = tid - 96;
        int rr = __ldg(&ranges[(bt*AA + a)*2]);
        sBase[a] = __ldg(&bonds[(bt*AA + rr)*2 + 1]);
    } else if (tid < 136) {
        int k = tid - 128;
        sPol[k] = (k < MD) ? __ldg(&donHvy[bt*MD + k]) : __ldg(&accI[bt*MA + (k - MD)]);
    } else if (tid >= 160) {             // warps 5-7: inter-block sep ballots
        int l = tid & 31;
        int w = (tid >> 5) - 5;
        int v = __ldg(&msep[(p*BB + b)*BB + w*32 + l]);
        unsigned m = __ballot_sync(0xFFFFFFFFu, v >= 4);
        if (l == 0) sBp[w] = m;
    }

    // ---------- stage j-chunk into shared (all threads, independent) ----------
    #pragma unroll
    for (int u = 0; u < CHUNK/256; u++) {
        int k = u*256 + tid;
        int j = j0 + k;
        int bj = j >> 5, aj = j & 31;
        int btj = __ldg(&btype[p*BB + bj]);
        int idx = btj*AA + aj;
        float4 pr = __ldg((const float4*)lkp + idx);   // ri, dgi, lami, vol
        const float* cp = coords + (pbase + j)*3;
        float4 q;
        q.x = __ldg(cp); q.y = __ldg(cp+1); q.z = __ldg(cp+2); q.w = pr.x;
        sJ[k] = q;
        sVol[k] = __ldg(&isH[idx]) ? 0.0f : pr.w;
    }
    __syncthreads();

    // ---------- phase 1: pd ballots (all warps) + site geometry (warps 0,1) ----------
    {
        int v = __ldg(&pd[(bt*AA + sPol[wid])*AA + lane]);
        unsigned m = __ballot_sync(0xFFFFFFFFu, v >= 4);
        if (lane == 0) sIm[wid] = m;
    }

    const bool isDon = (tid < MD);                      // warp 0 lanes 0-3
    const bool isAcc = (tid >= 32 && tid < 32 + MA);    // warp 1 lanes 0-3
    if (isDon | isAcc) {
        const int k = isDon ? tid : (MD + tid - 32);
        const float wdist = wgp[0], wang = wgp[1];
        const int pol = sPol[k];
        F3 w0v, w1v;
        bool valid;

        F3 c; c.x = sC[pol*3]; c.y = sC[pol*3+1]; c.z = sC[pol*3+2];

        if (isDon) {
            int hh = __ldg(&donH[bt*MD + k]);
            valid = (k < __ldg(&n_donH[bt]));
            F3 Hh; Hh.x = sC[hh*3]; Hh.y = sC[hh*3+1]; Hh.z = sC[hh*3+2];
            F3 dv = sub3(Hh, c);
            float s = wdist * rsqrtf(dot3(dv,dv) + 1e-12f);
            w0v.x = c.x + s*dv.x; w0v.y = c.y + s*dv.y; w0v.z = c.z + s*dv.z;
            w1v.x = 1e4f; w1v.y = 1e4f; w1v.z = 1e4f;   // donor water1 invalid sentinel
        } else {
            int m = k - MD;
            valid = (m < __ldg(&n_acc[bt]));
            int base  = sBase[pol];
            int base2 = sBase[base];
            F3 bz; bz.x = sC[base*3];  bz.y = sC[base*3+1];  bz.z = sC[base*3+2];
            F3 az; az.x = sC[base2*3]; az.y = sC[base2*3+1]; az.z = sC[base2*3+2];
            F3 e1 = norm3(sub3(c, bz));
            F3 nv = norm3(cross3(sub3(bz, az), e1));
            F3 e2 = cross3(nv, e1);
            int hy = __ldg(&hyb[bt*MA + m]);
            const float* tors = (hy == 0) ? sp2t : ((hy == 1) ? sp3t : ringt);
            float ct = cosf(wang), st = sinf(wang);
            float c1 = -wdist * ct;
            float t0 = tors[0], t1 = tors[1];
            float c2a = wdist * st * cosf(t0), c3a = wdist * st * sinf(t0);
            float c2b = wdist * st * cosf(t1), c3b = wdist * st * sinf(t1);
            w0v.x = c.x + c1*e1.x + c2a*e2.x + c3a*nv.x;
            w0v.y = c.y + c1*e1.y + c2a*e2.y + c3a*nv.y;
            w0v.z = c.z + c1*e1.z + c2a*e2.z + c3a*nv.z;
            w1v.x = c.x + c1*e1.x + c2b*e2.x + c3b*nv.x;
            w1v.y = c.y + c1*e1.y + c2b*e2.y + c3b*nv.y;
            w1v.z = c.z + c1*e1.z + c2b*e2.z + c3b*nv.z;
        }

        float4 pr = __ldg((const float4*)lkp + bt*AA + pol);  // ri, dgi, lami, vol
        float4 P4, W04, W14;
        if (valid) { P4.x = c.x; P4.y = c.y; P4.z = c.z; }
        else       { P4.x = 1e9f; P4.y = 1e9f; P4.z = 1e9f; }   // never within cutoff
        P4.w  = C_LK * pr.y / pr.z;       // Ki
        W04.x = w0v.x; W04.y = w0v.y; W04.z = w0v.z; W04.w = 1.0f / pr.z;  // inv_lami
        W14.x = w1v.x; W14.y = w1v.y; W14.z = w1v.z; W14.w = pr.x;         // ri
        sP [k] = P4;
        sW0[k] = W04;
        sW1[k] = W14;
    }
    __syncthreads();

    // ---------- transpose intra masks to per-aj site bytes ----------
    if (tid < AA) {
        unsigned byte = 0;
        #pragma unroll
        for (int i = 0; i < NPOLB; i++) byte |= ((sIm[i] >> tid) & 1u) << i;
        sSame[tid] = (unsigned char)byte;
    }
    __syncthreads();

    // ---------- phase 2: light loop (ILP) + bulk compaction ----------
    float xpx[NPOLB], xpy[NPOLB], xpz[NPOLB];
    #pragma unroll
    for (int i = 0; i < NPOLB; i++) {
        float4 P4 = sP[i];
        xpx[i] = P4.x; xpy[i] = P4.y; xpz[i] = P4.z;
    }
    const unsigned bp0 = sBp[0], bp1 = sBp[1], bp2 = sBp[2];

    const float cutoff = lkg[0];
    const float cut2   = cutoff * cutoff;
    const float ramp2  = lkg[1];
    const float c0     = lkg[2] + ramp2;   // d2_low + ramp2
    const float invr   = 1.0f / ramp2;

    float s0 = 0.0f, s1 = 0.0f;

    auto processE = [&](int e) {
        int i  = e >> 10;
        int jj = e & 1023;
        float4 J  = sJ[jj];
        float  vj = sVol[jj];
        float4 Pq = sP[i];
        float4 W0 = sW0[i];
        float4 W1 = sW1[i];
        float dx = Pq.x - J.x, dy = Pq.y - J.y, dz = Pq.z - J.z;
        float d2 = fmaf(dx, dx, fmaf(dy, dy, dz*dz));
        d2 = fmaxf(d2, 0.01f);
        float d  = sqrtf(d2);
        float x  = (d - W1.w - J.w) * W0.w;
        float lk = __fdividef(Pq.w * vj * __expf(-x*x), d2);
        float ax = W0.x - J.x, ay = W0.y - J.y, az = W0.z - J.z;
        float d2a = fmaf(ax, ax, fmaf(ay, ay, az*az));
        float bx = W1.x - J.x, by = W1.y - J.y, bz = W1.z - J.z;
        float d2b = fmaf(bx, bx, fmaf(by, by, bz*bz));
        float dm = fminf(d2a, d2b);
        float wt = __saturatef((c0 - dm) * invr);
        float fr = wt * wt * (3.0f - 2.0f*wt);
        s0 += lk;
        s1 += lk * fr;
    };

    int qc = 0;                              // warp-uniform queue count
    const unsigned ltm = (1u << lane) - 1u;

    #pragma unroll
    for (int u = 0; u < CHUNK/256; u++) {
        int jj = u*256 + tid;
        int j  = j0 + jj;
        int bj = j >> 5;                     // warp-uniform
        int aj = jj & 31;
        bool same = (bj == b);
        unsigned inter =
            ((bj < 32) ? (bp0 >> bj) : (bj < 64) ? (bp1 >> (bj-32)) : (bp2 >> (bj-64))) & 1u;
        if (!same && !inter) continue;       // warp-uniform skip

        float4 J = sJ[jj];
        float vj = sVol[jj];
        unsigned mask = (vj > 0.0f) ? (same ? (unsigned)sSame[aj] : 0xFFu) : 0u;

        // --- all 8 distance tests with full ILP, no sync ops ---
        unsigned hit = 0;
        #pragma unroll
        for (int i = 0; i < NPOLB; i++) {
            float dx = xpx[i] - J.x;
            float dy = xpy[i] - J.y;
            float dz = xpz[i] - J.z;
            float d2 = fmaf(dx, dx, fmaf(dy, dy, dz*dz));
            hit |= (unsigned)(d2 < cut2) << i;
        }
        hit &= mask;

        unsigned any = __ballot_sync(0xFFFFFFFFu, hit != 0);
        if (any) {
            // --- 8 independent ballots (latencies overlap), then offset tree ---
            unsigned mv[NPOLB];
            #pragma unroll
            for (int i = 0; i < NPOLB; i++)
                mv[i] = __ballot_sync(0xFFFFFFFFu, (hit >> i) & 1u);

            int base = qc;
            #pragma unroll
            for (int i = 0; i < NPOLB; i++) {
                if ((hit >> i) & 1u)
                    sQ[wid][base + __popc(mv[i] & ltm)] = (i << 10) | jj;
                base += __popc(mv[i]);
            }
            qc = base;
            while (qc >= 32) {               // warp-uniform flush, full efficiency
                qc -= 32;
                processE(sQ[wid][qc + lane]);
            }
        }
    }
    if (lane < qc) processE(sQ[wid][lane]);  // drain leftovers (<32)

    // ---------- reduction + self-resetting global accumulation (single node) ----------
    #pragma unroll
    for (int off = 16; off > 0; off >>= 1) {
        s0 += __shfl_xor_sync(0xFFFFFFFFu, s0, off);
        s1 += __shfl_xor_sync(0xFFFFFFFFu, s1, off);
    }
    if (lane == 0) { sred[0][wid] = s0; sred[1][wid] = s1; }
    __syncthreads();
    if (tid == 0) {
        float t0 = 0.f, t1 = 0.f;
        #pragma unroll
        for (int w = 0; w < 8; w++) { t0 += sred[0][w]; t1 += sred[1][w]; }
        atomicAdd(&g_acc[p],     t0);
        atomicAdd(&g_acc[2 + p], t1);
        __threadfence();
        unsigned done = atomicAdd(&g_cnt, 1u);
        if (done == NBLK - 1) {
            out[0] = atomicExch(&g_acc[0], 0.0f);
            out[1] = atomicExch(&g_acc[1], 0.0f);
            out[2] = atomicExch(&g_acc[2], 0.0f);
            out[3] = atomicExch(&g_acc[3], 0.0f);
            atomicExch(&g_cnt, 0u);
        }
    }
}

extern "C" void kernel_launch(void* const* d_in, const int* in_sizes, int n_in,
                              void* d_out, int out_size)
{
    const float* coords = (const float*)d_in[0];
    const int*   btype  = (const int*)  d_in[1];
    const int*   msep   = (const int*)  d_in[2];
    /* d_in[3] = bt_n_atoms (unused, always A) */
    const int*   bonds  = (const int*)  d_in[4];
    const int*   ranges = (const int*)  d_in[5];
    const int*   ndonH  = (const int*)  d_in[6];
    const int*   nacc   = (const int*)  d_in[7];
    const int*   donH   = (const int*)  d_in[8];
    const int*   donHvy = (const int*)  d_in[9];
    const int*   accI   = (const int*)  d_in[10];
    const int*   hyb    = (const int*)  d_in[11];
    const int*   isH    = (const int*)  d_in[12];
    const float* lkp    = (const float*)d_in[13];
    const int*   pd     = (const int*)  d_in[14];
    const float* lkg    = (const float*)d_in[15];
    const float* wgp    = (const float*)d_in[16];
    const float* sp2t   = (const float*)d_in[17];
    const float* sp3t   = (const float*)d_in[18];
    const float* ringt  = (const float*)d_in[19];
    float* out = (float*)d_out;

    dim3 grid(PP*BB, JSPLIT);
    lkball_fused_kernel<<<grid, 256>>>(coords, btype, msep, bonds, ranges,
                                       ndonH, nacc, donH, donHvy, accI, hyb, isH,
                                       lkp, pd, lkg, wgp, sp2t, sp3t, ringt, out);
}